// round 3
// baseline (speedup 1.0000x reference)
#include <cuda_runtime.h>
#include <math.h>
#include <stdint.h>

#define NN   4096
#define EMBD 32
#define BQ   8192
#define KNN  20
#define FULL 0xffffffffu

typedef unsigned long long u64;
typedef unsigned int u32;

// Scratch (device globals; no allocation in kernel_launch)
__device__ float g_D2[(size_t)NN * NN];        // 64 MB, reused per branch
__device__ float g_norm[2 * NN];
__device__ int   g_nbr_idx[2 * NN * KNN];
__device__ float g_nbr_d2[2 * NN * KNN];

// ---------------------------------------------------------------------------
// packed f32x2 helpers (Blackwell FFMA2 path — PTX only)
// ---------------------------------------------------------------------------
__device__ __forceinline__ u64 pack2(float lo, float hi) {
    u64 r;
    asm("mov.b64 %0, {%1, %2};" : "=l"(r) : "f"(lo), "f"(hi));
    return r;
}
__device__ __forceinline__ void unpack2(u64 v, float& lo, float& hi) {
    asm("mov.b64 {%0, %1}, %2;" : "=f"(lo), "=f"(hi) : "l"(v));
}
__device__ __forceinline__ void ffma2(u64& d, u64 a, u64 b) {
    asm("fma.rn.f32x2 %0, %1, %2, %0;" : "+l"(d) : "l"(a), "l"(b));
}

// ---------------------------------------------------------------------------
// ||e||^2 per row for both embedding tables
// ---------------------------------------------------------------------------
__global__ void norms_kernel(const float* __restrict__ e1,
                             const float* __restrict__ e2) {
    int r = blockIdx.x * blockDim.x + threadIdx.x;
    if (r >= 2 * NN) return;
    const float* e = (r < NN) ? e1 : e2;
    int row = r & (NN - 1);
    const float4* p = reinterpret_cast<const float4*>(e + (size_t)row * EMBD);
    float s = 0.f;
#pragma unroll
    for (int i = 0; i < 8; i++) {
        float4 v = p[i];
        s += v.x * v.x + v.y * v.y + v.z * v.z + v.w * v.w;
    }
    g_norm[r] = s;
}

// ---------------------------------------------------------------------------
// All-pairs squared distances, one branch. Symmetric: upper-triangle tiles
// only (528 CTAs launched via packed linear index), write tile + transpose.
// fp32, 128x128 tile per CTA, 8x8 per thread, K=32 slab, FFMA2 inner loop.
// ---------------------------------------------------------------------------
__global__ void __launch_bounds__(256, 2) knn_gemm(const float* __restrict__ emb,
                                                   int branch) {
    // linear -> (bx >= by) triangle
    int l = blockIdx.x;
    int bx = (int)((sqrtf(8.f * (float)l + 1.f) - 1.f) * 0.5f);
    while ((bx + 1) * (bx + 2) / 2 <= l) bx++;
    while (bx * (bx + 1) / 2 > l) bx--;
    int by = l - bx * (bx + 1) / 2;

    __shared__ float As[EMBD][132];
    __shared__ float Bs[EMBD][132];

    const int tid = threadIdx.x;          // 256 threads
    const int tx = tid & 15, ty = tid >> 4;
    const int i0 = by * 128, j0 = bx * 128;

    const float4* ea = reinterpret_cast<const float4*>(emb) + (size_t)i0 * 8;
    const float4* eb = reinterpret_cast<const float4*>(emb) + (size_t)j0 * 8;

#pragma unroll
    for (int l2 = 0; l2 < 4; l2++) {
        int lin = l2 * 256 + tid;         // 1024 float4s = 128 rows x 8
        int row = lin >> 3, c4 = lin & 7;
        float4 va = ea[row * 8 + c4];
        As[c4 * 4 + 0][row] = va.x; As[c4 * 4 + 1][row] = va.y;
        As[c4 * 4 + 2][row] = va.z; As[c4 * 4 + 3][row] = va.w;
        float4 vb = eb[row * 8 + c4];
        Bs[c4 * 4 + 0][row] = vb.x; Bs[c4 * 4 + 1][row] = vb.y;
        Bs[c4 * 4 + 2][row] = vb.z; Bs[c4 * 4 + 3][row] = vb.w;
    }
    __syncthreads();

    u64 accp[8][4];                       // 8 rows x 4 col-pairs, packed f32x2
#pragma unroll
    for (int r = 0; r < 8; r++)
#pragma unroll
        for (int c = 0; c < 4; c++) accp[r][c] = 0ull;

#pragma unroll
    for (int k = 0; k < EMBD; k++) {
        float a_[8], b_[8];
        *reinterpret_cast<float4*>(&a_[0]) = *reinterpret_cast<const float4*>(&As[k][ty * 8]);
        *reinterpret_cast<float4*>(&a_[4]) = *reinterpret_cast<const float4*>(&As[k][ty * 8 + 4]);
        *reinterpret_cast<float4*>(&b_[0]) = *reinterpret_cast<const float4*>(&Bs[k][tx * 8]);
        *reinterpret_cast<float4*>(&b_[4]) = *reinterpret_cast<const float4*>(&Bs[k][tx * 8 + 4]);
        u64 bp[4];
#pragma unroll
        for (int c = 0; c < 4; c++) bp[c] = pack2(b_[2 * c], b_[2 * c + 1]);
#pragma unroll
        for (int r = 0; r < 8; r++) {
            u64 as_ = pack2(a_[r], a_[r]);
#pragma unroll
            for (int c = 0; c < 4; c++) ffma2(accp[r][c], as_, bp[c]);
        }
    }

    float acc[8][8];
#pragma unroll
    for (int r = 0; r < 8; r++)
#pragma unroll
        for (int c = 0; c < 4; c++) unpack2(accp[r][c], acc[r][2 * c], acc[r][2 * c + 1]);

    const float* nrm = g_norm + branch * NN;
    float na[8], nb[8];
#pragma unroll
    for (int r = 0; r < 8; r++) na[r] = nrm[i0 + ty * 8 + r];
#pragma unroll
    for (int c = 0; c < 8; c++) nb[c] = nrm[j0 + tx * 8 + c];

#pragma unroll
    for (int r = 0; r < 8; r++) {
        int gi = i0 + ty * 8 + r;
#pragma unroll
        for (int c = 0; c < 8; c++) {
            int gj = j0 + tx * 8 + c;
            float d = na[r] + nb[c] - 2.f * acc[r][c];
            acc[r][c] = (gi == gj) ? 3.4e38f : d;
        }
    }

#pragma unroll
    for (int r = 0; r < 8; r++) {
        int gi = i0 + ty * 8 + r;
        float* dst = g_D2 + (size_t)gi * NN + j0 + tx * 8;
        *reinterpret_cast<float4*>(dst)     = make_float4(acc[r][0], acc[r][1], acc[r][2], acc[r][3]);
        *reinterpret_cast<float4*>(dst + 4) = make_float4(acc[r][4], acc[r][5], acc[r][6], acc[r][7]);
    }
    if (bx != by) {
#pragma unroll
        for (int c = 0; c < 8; c++) {
            int gj = j0 + tx * 8 + c;
            float* dst = g_D2 + (size_t)gj * NN + i0 + ty * 8;
            *reinterpret_cast<float4*>(dst)     = make_float4(acc[0][c], acc[1][c], acc[2][c], acc[3][c]);
            *reinterpret_cast<float4*>(dst + 4) = make_float4(acc[4][c], acc[5][c], acc[6][c], acc[7][c]);
        }
    }
}

// ---------------------------------------------------------------------------
// Selection helpers. key = orderable(d2)<<32 | (NN-1-j): ties prefer larger j
// (matches stable ascending argsort window semantics of the reference).
// ---------------------------------------------------------------------------
__device__ __forceinline__ u32 ord32(float f) {
    u32 u = __float_as_uint(f);
    return u ^ ((u32)((int)u >> 31) | 0x80000000u);
}
__device__ __forceinline__ u64 make_key(float f, int j) {
    return ((u64)ord32(f) << 32) | (u32)(NN - 1 - j);
}
__device__ __forceinline__ float key_d2(u64 k) {
    u32 u = (u32)(k >> 32);
    return (u & 0x80000000u) ? __uint_as_float(u & 0x7fffffffu)
                             : __uint_as_float(~u);
}

// Exact streaming fallback (warp-distributed sorted top-32 list)
__device__ __forceinline__ void sel_batch(u64 k, u64& list, u64& tau, int lane) {
    unsigned m = __ballot_sync(FULL, k < tau);
    while (m) {
        int src = __ffs(m) - 1; m &= m - 1;
        u64 v = __shfl_sync(FULL, k, src);
        if (v < tau) {
            unsigned lt = __ballot_sync(FULL, list < v);
            int pos = __popc(lt);
            u64 up1 = __shfl_up_sync(FULL, list, 1);
            if (lane == pos)      list = v;
            else if (lane > pos)  list = up1;
            tau = __shfl_sync(FULL, list, 31);
        }
    }
}

__device__ void exact_row_select(const float4* __restrict__ row,
                                 int lane, int branch, int gw) {
    float4 v = row[lane];
    int jb = lane * 4;
    u64 list = make_key(v.x, jb);
#pragma unroll
    for (int k = 2; k <= 32; k <<= 1) {
#pragma unroll
        for (int j = k >> 1; j > 0; j >>= 1) {
            u64 o = __shfl_xor_sync(FULL, list, j);
            bool up = ((lane & k) == 0) || (k == 32);
            bool lower = ((lane & j) == 0);
            bool take_min = (lower == up);
            u64 mn = (o < list) ? o : list;
            u64 mx = (o < list) ? list : o;
            list = take_min ? mn : mx;
        }
    }
    u64 tau = __shfl_sync(FULL, list, 31);
    sel_batch(make_key(v.y, jb + 1), list, tau, lane);
    sel_batch(make_key(v.z, jb + 2), list, tau, lane);
    sel_batch(make_key(v.w, jb + 3), list, tau, lane);
    for (int it = 1; it < NN / 128; ++it) {
        v = row[it * 32 + lane];
        jb = it * 128 + lane * 4;
        sel_batch(make_key(v.x, jb + 0), list, tau, lane);
        sel_batch(make_key(v.y, jb + 1), list, tau, lane);
        sel_batch(make_key(v.z, jb + 2), list, tau, lane);
        sel_batch(make_key(v.w, jb + 3), list, tau, lane);
    }
    if (lane < KNN) {
        int o = (branch * NN + gw) * KNN + lane;
        g_nbr_idx[o] = NN - 1 - (int)(u32)list;
        g_nbr_d2[o] = key_d2(list);
    }
}

// ---------------------------------------------------------------------------
// Fast top-KNN: per-lane sorted top-6 (no collectives in scan), warp merge via
// 20 extract-min rounds, exact-fallback if any lane's 6th key < tau20.
// ---------------------------------------------------------------------------
__global__ void knn_select(int branch) {
    int gw = blockIdx.x * (blockDim.x >> 5) + (threadIdx.x >> 5);
    int lane = threadIdx.x & 31;
    if (gw >= NN) return;

    const float4* row = reinterpret_cast<const float4*>(g_D2 + (size_t)gw * NN);

    u64 k0 = ~0ull, k1 = ~0ull, k2 = ~0ull, k3 = ~0ull, k4 = ~0ull, k5 = ~0ull;

#pragma unroll 4
    for (int it = 0; it < NN / 128; ++it) {
        float4 v = row[it * 32 + lane];
        int jb = it * 128 + lane * 4;
        float d[4] = {v.x, v.y, v.z, v.w};
#pragma unroll
        for (int e = 0; e < 4; e++) {
            u64 key = make_key(d[e], jb + e);
            if (key < k5) {
                if (key < k4) {
                    k5 = k4;
                    if (key < k3) {
                        k4 = k3;
                        if (key < k2) {
                            k3 = k2;
                            if (key < k1) {
                                k2 = k1;
                                if (key < k0) { k1 = k0; k0 = key; }
                                else k1 = key;
                            } else k2 = key;
                        } else k3 = key;
                    } else k4 = key;
                } else k5 = key;
            }
        }
    }

    // merge: 20 extract-min rounds over lanes' sorted 6-lists
    int cnt = 0;
    u64 tau = ~0ull;
    int obase = (branch * NN + gw) * KNN;
#pragma unroll
    for (int s = 0; s < KNN; s++) {
        u64 head = (cnt == 0) ? k0 : (cnt == 1) ? k1 : (cnt == 2) ? k2 :
                   (cnt == 3) ? k3 : (cnt == 4) ? k4 : (cnt == 5) ? k5 : ~0ull;
        u64 m = head;
#pragma unroll
        for (int off = 16; off > 0; off >>= 1) {
            u64 o = __shfl_xor_sync(FULL, m, off);
            if (o < m) m = o;
        }
        if (head == m) {               // unique keys -> exactly one winner
            g_nbr_idx[obase + s] = NN - 1 - (int)(u32)m;
            g_nbr_d2[obase + s] = key_d2(m);
            cnt++;
        }
        tau = m;                       // after loop: 20th smallest candidate
    }

    // exactness check: any lane whose 6th-kept key beats tau may have dropped
    // a true top-20 element -> redo this row exactly (~0.14% of rows).
    if (__ballot_sync(FULL, k5 < tau))
        exact_row_select(row, lane, branch, gw);
}

// ---------------------------------------------------------------------------
// Per-query gather + features + MLP. One warp per query.
// ---------------------------------------------------------------------------
__device__ __forceinline__ float warp_sum(float v) {
#pragma unroll
    for (int off = 16; off > 0; off >>= 1)
        v += __shfl_xor_sync(FULL, v, off);
    return v;
}

__global__ void gather_mlp(const int* __restrict__ timev,
                           const int* __restrict__ idx1v,
                           const int* __restrict__ idx2v,
                           const float* __restrict__ residuals,
                           const float* __restrict__ means,
                           const float* __restrict__ stds,
                           const float* __restrict__ W1,
                           const float* __restrict__ b1,
                           const float* __restrict__ Wm,
                           const float* __restrict__ bm,
                           const float* __restrict__ Ws,
                           const float* __restrict__ bs,
                           float* __restrict__ out) {
    int q = (blockIdx.x * blockDim.x + threadIdx.x) >> 5;
    int lane = threadIdx.x & 31;
    if (q >= BQ) return;

    int t = timev[q], a = idx1v[q], c = idx2v[q];
    size_t base = (size_t)t * NN * NN;

    float f[8];
#pragma unroll
    for (int br = 0; br < 2; ++br) {
        int row = br ? c : a;
        float wgt = 0.f, sel = 0.f;
        if (lane < KNN) {
            int o = (br * NN + row) * KNN + lane;
            int j = g_nbr_idx[o];
            float d2 = g_nbr_d2[o];
            float sim = sqrtf(fmaxf(d2, 0.f)) + 0.001f;
            wgt = expf(-sim);
            sel = br ? residuals[base + (size_t)a * NN + j]     // f2: row context
                     : residuals[base + (size_t)j * NN + c];    // f1: column context
        }
        float sw  = warp_sum(wgt * sel);
        float wsm = warp_sum(wgt);
        float ss  = warp_sum(sel);
        float s2  = warp_sum(sel * sel);
        f[br * 3 + 0] = sw / wsm;
        f[br * 3 + 1] = wsm;
        f[br * 3 + 2] = sqrtf(fmaxf((s2 - ss * ss / (float)KNN) / (float)(KNN - 1), 0.f));
    }
    f[6] = means[base + (size_t)a * NN + c];
    f[7] = stds[base + (size_t)a * NN + c];

    float om = 0.f, osum = 0.f;
#pragma unroll
    for (int r = 0; r < 2; r++) {
        int k = lane + r * 32;
        float h = b1[k];
#pragma unroll
        for (int ff = 0; ff < 8; ++ff) h = fmaf(f[ff], W1[k * 8 + ff], h);
        h = fmaxf(h, 0.f);
        om   = fmaf(h, Wm[k], om);
        osum = fmaf(h, Ws[k], osum);
    }
    om = warp_sum(om);
    osum = warp_sum(osum);
    if (lane == 0) {
        out[q]      = om   + bm[0];
        out[BQ + q] = osum + bs[0];
    }
}

// ---------------------------------------------------------------------------
extern "C" void kernel_launch(void* const* d_in, const int* in_sizes, int n_in,
                              void* d_out, int out_size) {
    const int*   timev = (const int*)d_in[0];
    const int*   idx1  = (const int*)d_in[1];
    const int*   idx2  = (const int*)d_in[2];
    const float* resid = (const float*)d_in[3];
    const float* means = (const float*)d_in[4];
    const float* stds  = (const float*)d_in[5];
    const float* emb1  = (const float*)d_in[6];
    const float* emb2  = (const float*)d_in[7];
    const float* W1    = (const float*)d_in[8];
    const float* b1    = (const float*)d_in[9];
    const float* Wm    = (const float*)d_in[10];
    const float* bm    = (const float*)d_in[11];
    const float* Ws    = (const float*)d_in[12];
    const float* bs    = (const float*)d_in[13];
    float* out = (float*)d_out;

    norms_kernel<<<32, 256>>>(emb1, emb2);

    const int TRI = (NN / 128) * (NN / 128 + 1) / 2;   // 528 triangle CTAs
    // branch 0 (emb1)
    knn_gemm<<<TRI, 256>>>(emb1, 0);
    knn_select<<<NN / 8, 256>>>(0);
    // branch 1 (emb2)
    knn_gemm<<<TRI, 256>>>(emb2, 1);
    knn_select<<<NN / 8, 256>>>(1);

    gather_mlp<<<BQ / 8, 256>>>(timev, idx1, idx2, resid, means, stds,
                                W1, b1, Wm, bm, Ws, bs, out);
}

// round 4
// speedup vs baseline: 1.0101x; 1.0101x over previous
#include <cuda_runtime.h>
#include <math.h>
#include <stdint.h>

#define NN   4096
#define EMBD 32
#define BQ   8192
#define KNN  20
#define FULL 0xffffffffu

typedef unsigned long long u64;
typedef unsigned int u32;

// Scratch (device globals; no allocation in kernel_launch)
__device__ float g_D2[(size_t)NN * NN];        // 64 MB, reused per branch
__device__ float g_norm[2 * NN];
__device__ int   g_nbr_idx[2 * NN * KNN];
__device__ float g_nbr_d2[2 * NN * KNN];

// ---------------------------------------------------------------------------
// packed f32x2 helpers (Blackwell FFMA2 path — PTX only)
// ---------------------------------------------------------------------------
__device__ __forceinline__ u64 pack2(float lo, float hi) {
    u64 r;
    asm("mov.b64 %0, {%1, %2};" : "=l"(r) : "f"(lo), "f"(hi));
    return r;
}
__device__ __forceinline__ void unpack2(u64 v, float& lo, float& hi) {
    asm("mov.b64 {%0, %1}, %2;" : "=f"(lo), "=f"(hi) : "l"(v));
}
__device__ __forceinline__ void ffma2(u64& d, u64 a, u64 b) {
    asm("fma.rn.f32x2 %0, %1, %2, %0;" : "+l"(d) : "l"(a), "l"(b));
}

// ---------------------------------------------------------------------------
// ||e||^2 per row for both embedding tables
// ---------------------------------------------------------------------------
__global__ void norms_kernel(const float* __restrict__ e1,
                             const float* __restrict__ e2) {
    int r = blockIdx.x * blockDim.x + threadIdx.x;
    if (r >= 2 * NN) return;
    const float* e = (r < NN) ? e1 : e2;
    int row = r & (NN - 1);
    const float4* p = reinterpret_cast<const float4*>(e + (size_t)row * EMBD);
    float s = 0.f;
#pragma unroll
    for (int i = 0; i < 8; i++) {
        float4 v = p[i];
        s += v.x * v.x + v.y * v.y + v.z * v.z + v.w * v.w;
    }
    g_norm[r] = s;
}

// ---------------------------------------------------------------------------
// All-pairs squared distances, one branch. Full grid, coalesced stores only.
// fp32, 128x128 tile per CTA, 8x8 per thread, K=32 slab, FFMA2 inner loop.
// ---------------------------------------------------------------------------
__global__ void __launch_bounds__(256, 2) knn_gemm(const float* __restrict__ emb,
                                                   int branch) {
    __shared__ float As[EMBD][132];
    __shared__ float Bs[EMBD][132];

    const int tid = threadIdx.x;          // 256 threads
    const int tx = tid & 15, ty = tid >> 4;
    const int i0 = blockIdx.y * 128, j0 = blockIdx.x * 128;

    const float4* ea = reinterpret_cast<const float4*>(emb) + (size_t)i0 * 8;
    const float4* eb = reinterpret_cast<const float4*>(emb) + (size_t)j0 * 8;

#pragma unroll
    for (int l = 0; l < 4; l++) {
        int lin = l * 256 + tid;          // 1024 float4s = 128 rows x 8
        int row = lin >> 3, c4 = lin & 7;
        float4 va = ea[row * 8 + c4];
        As[c4 * 4 + 0][row] = va.x; As[c4 * 4 + 1][row] = va.y;
        As[c4 * 4 + 2][row] = va.z; As[c4 * 4 + 3][row] = va.w;
        float4 vb = eb[row * 8 + c4];
        Bs[c4 * 4 + 0][row] = vb.x; Bs[c4 * 4 + 1][row] = vb.y;
        Bs[c4 * 4 + 2][row] = vb.z; Bs[c4 * 4 + 3][row] = vb.w;
    }
    __syncthreads();

    u64 accp[8][4];                       // 8 rows x 4 col-pairs, packed f32x2
#pragma unroll
    for (int r = 0; r < 8; r++)
#pragma unroll
        for (int c = 0; c < 4; c++) accp[r][c] = 0ull;

#pragma unroll
    for (int k = 0; k < EMBD; k++) {
        float a_[8], b_[8];
        *reinterpret_cast<float4*>(&a_[0]) = *reinterpret_cast<const float4*>(&As[k][ty * 8]);
        *reinterpret_cast<float4*>(&a_[4]) = *reinterpret_cast<const float4*>(&As[k][ty * 8 + 4]);
        *reinterpret_cast<float4*>(&b_[0]) = *reinterpret_cast<const float4*>(&Bs[k][tx * 8]);
        *reinterpret_cast<float4*>(&b_[4]) = *reinterpret_cast<const float4*>(&Bs[k][tx * 8 + 4]);
        u64 bp[4];
#pragma unroll
        for (int c = 0; c < 4; c++) bp[c] = pack2(b_[2 * c], b_[2 * c + 1]);
#pragma unroll
        for (int r = 0; r < 8; r++) {
            u64 as_ = pack2(a_[r], a_[r]);
#pragma unroll
            for (int c = 0; c < 4; c++) ffma2(accp[r][c], as_, bp[c]);
        }
    }

    const float* nrm = g_norm + branch * NN;
    float nb[8];
#pragma unroll
    for (int c = 0; c < 8; c++) nb[c] = nrm[j0 + tx * 8 + c];

    // per-row epilogue: unpack, d2 = n_i + n_j - 2*dot, self masked, store
#pragma unroll
    for (int r = 0; r < 8; r++) {
        int gi = i0 + ty * 8 + r;
        float na = nrm[gi];
        float o[8];
#pragma unroll
        for (int c = 0; c < 4; c++) unpack2(accp[r][c], o[2 * c], o[2 * c + 1]);
#pragma unroll
        for (int c = 0; c < 8; c++) {
            int gj = j0 + tx * 8 + c;
            float d = na + nb[c] - 2.f * o[c];
            o[c] = (gi == gj) ? 3.4e38f : d;
        }
        float* dst = g_D2 + (size_t)gi * NN + j0 + tx * 8;
        *reinterpret_cast<float4*>(dst)     = make_float4(o[0], o[1], o[2], o[3]);
        *reinterpret_cast<float4*>(dst + 4) = make_float4(o[4], o[5], o[6], o[7]);
    }
}

// ---------------------------------------------------------------------------
// Selection. key = orderable(d2)<<32 | (NN-1-j): ties prefer larger j
// (matches stable ascending argsort window semantics of the reference).
// Warp-distributed sorted top-32 list, one u64 key per lane, ascending.
// ---------------------------------------------------------------------------
__device__ __forceinline__ u32 ord32(float f) {
    u32 u = __float_as_uint(f);
    return u ^ ((u32)((int)u >> 31) | 0x80000000u);
}
__device__ __forceinline__ u64 make_key(float f, int j) {
    return ((u64)ord32(f) << 32) | (u32)(NN - 1 - j);
}
__device__ __forceinline__ float key_d2(u64 k) {
    u32 u = (u32)(k >> 32);
    return (u & 0x80000000u) ? __uint_as_float(u & 0x7fffffffu)
                             : __uint_as_float(~u);
}

// warp-uniform insert of a broadcast key v into the distributed sorted list
__device__ __forceinline__ void insert_bcast(u64 v, u64& list, u64& tau,
                                             float& tau_d2, int lane) {
    if (v < tau) {
        unsigned lt = __ballot_sync(FULL, list < v);
        int pos = __popc(lt);
        u64 up1 = __shfl_up_sync(FULL, list, 1);
        if (lane == pos)      list = v;
        else if (lane > pos)  list = up1;
        tau = __shfl_sync(FULL, list, 31);
        tau_d2 = key_d2(tau);
    }
}

// per-lane key insert (used for the unfiltered first batch)
__device__ __forceinline__ void sel_elem(u64 k, u64& list, u64& tau,
                                         float& tau_d2, int lane) {
    unsigned m = __ballot_sync(FULL, k < tau);
    while (m) {
        int src = __ffs(m) - 1; m &= m - 1;
        u64 v = __shfl_sync(FULL, k, src);
        insert_bcast(v, list, tau, tau_d2, lane);
    }
}

__global__ void knn_select(int branch) {
    int gw = blockIdx.x * (blockDim.x >> 5) + (threadIdx.x >> 5);
    int lane = threadIdx.x & 31;
    if (gw >= NN) return;

    const float4* row = reinterpret_cast<const float4*>(g_D2 + (size_t)gw * NN);

    // init list from elements j = lane*4 of the first 128-element batch
    float4 v = row[lane];
    int jb = lane * 4;
    u64 list = make_key(v.x, jb);

    // bitonic sort 32 keys ascending across lanes
#pragma unroll
    for (int k = 2; k <= 32; k <<= 1) {
#pragma unroll
        for (int j = k >> 1; j > 0; j >>= 1) {
            u64 o = __shfl_xor_sync(FULL, list, j);
            bool up = ((lane & k) == 0) || (k == 32);
            bool lower = ((lane & j) == 0);
            bool take_min = (lower == up);
            u64 mn = (o < list) ? o : list;
            u64 mx = (o < list) ? list : o;
            list = take_min ? mn : mx;
        }
    }
    u64 tau = __shfl_sync(FULL, list, 31);
    float tau_d2 = key_d2(tau);

    sel_elem(make_key(v.y, jb + 1), list, tau, tau_d2, lane);
    sel_elem(make_key(v.z, jb + 2), list, tau, tau_d2, lane);
    sel_elem(make_key(v.w, jb + 3), list, tau, tau_d2, lane);

    // main scan with min4 prefilter: one ballot per float4, no keys on the
    // common path. "<=" catches index-tiebreak equality; exact u64 key check
    // happens inside insert_bcast.
    for (int it = 1; it < NN / 128; ++it) {
        v = row[it * 32 + lane];
        float mn4 = fminf(fminf(v.x, v.y), fminf(v.z, v.w));
        unsigned trig = __ballot_sync(FULL, mn4 <= tau_d2);
        while (trig) {
            int src = __ffs(trig) - 1; trig &= trig - 1;
            float wx = __shfl_sync(FULL, v.x, src);
            float wy = __shfl_sync(FULL, v.y, src);
            float wz = __shfl_sync(FULL, v.z, src);
            float ww = __shfl_sync(FULL, v.w, src);
            int j0 = it * 128 + src * 4;
            insert_bcast(make_key(wx, j0 + 0), list, tau, tau_d2, lane);
            insert_bcast(make_key(wy, j0 + 1), list, tau, tau_d2, lane);
            insert_bcast(make_key(wz, j0 + 2), list, tau, tau_d2, lane);
            insert_bcast(make_key(ww, j0 + 3), list, tau, tau_d2, lane);
        }
    }

    // lanes 0..19 hold the top-20 (ascending d2); decode and store
    if (lane < KNN) {
        int o = (branch * NN + gw) * KNN + lane;
        g_nbr_idx[o] = NN - 1 - (int)(u32)list;
        g_nbr_d2[o] = key_d2(list);
    }
}

// ---------------------------------------------------------------------------
// Per-query gather + features + MLP. One warp per query.
// ---------------------------------------------------------------------------
__device__ __forceinline__ float warp_sum(float v) {
#pragma unroll
    for (int off = 16; off > 0; off >>= 1)
        v += __shfl_xor_sync(FULL, v, off);
    return v;
}

__global__ void gather_mlp(const int* __restrict__ timev,
                           const int* __restrict__ idx1v,
                           const int* __restrict__ idx2v,
                           const float* __restrict__ residuals,
                           const float* __restrict__ means,
                           const float* __restrict__ stds,
                           const float* __restrict__ W1,
                           const float* __restrict__ b1,
                           const float* __restrict__ Wm,
                           const float* __restrict__ bm,
                           const float* __restrict__ Ws,
                           const float* __restrict__ bs,
                           float* __restrict__ out) {
    int q = (blockIdx.x * blockDim.x + threadIdx.x) >> 5;
    int lane = threadIdx.x & 31;
    if (q >= BQ) return;

    int t = timev[q], a = idx1v[q], c = idx2v[q];
    size_t base = (size_t)t * NN * NN;

    float f[8];
#pragma unroll
    for (int br = 0; br < 2; ++br) {
        int row = br ? c : a;
        float wgt = 0.f, sel = 0.f;
        if (lane < KNN) {
            int o = (br * NN + row) * KNN + lane;
            int j = g_nbr_idx[o];
            float d2 = g_nbr_d2[o];
            float sim = sqrtf(fmaxf(d2, 0.f)) + 0.001f;
            wgt = expf(-sim);
            sel = br ? residuals[base + (size_t)a * NN + j]     // f2: row context
                     : residuals[base + (size_t)j * NN + c];    // f1: column context
        }
        float sw  = warp_sum(wgt * sel);
        float wsm = warp_sum(wgt);
        float ss  = warp_sum(sel);
        float s2  = warp_sum(sel * sel);
        f[br * 3 + 0] = sw / wsm;
        f[br * 3 + 1] = wsm;
        f[br * 3 + 2] = sqrtf(fmaxf((s2 - ss * ss / (float)KNN) / (float)(KNN - 1), 0.f));
    }
    f[6] = means[base + (size_t)a * NN + c];
    f[7] = stds[base + (size_t)a * NN + c];

    float om = 0.f, osum = 0.f;
#pragma unroll
    for (int r = 0; r < 2; r++) {
        int k = lane + r * 32;
        float h = b1[k];
#pragma unroll
        for (int ff = 0; ff < 8; ++ff) h = fmaf(f[ff], W1[k * 8 + ff], h);
        h = fmaxf(h, 0.f);
        om   = fmaf(h, Wm[k], om);
        osum = fmaf(h, Ws[k], osum);
    }
    om = warp_sum(om);
    osum = warp_sum(osum);
    if (lane == 0) {
        out[q]      = om   + bm[0];
        out[BQ + q] = osum + bs[0];
    }
}

// ---------------------------------------------------------------------------
extern "C" void kernel_launch(void* const* d_in, const int* in_sizes, int n_in,
                              void* d_out, int out_size) {
    const int*   timev = (const int*)d_in[0];
    const int*   idx1  = (const int*)d_in[1];
    const int*   idx2  = (const int*)d_in[2];
    const float* resid = (const float*)d_in[3];
    const float* means = (const float*)d_in[4];
    const float* stds  = (const float*)d_in[5];
    const float* emb1  = (const float*)d_in[6];
    const float* emb2  = (const float*)d_in[7];
    const float* W1    = (const float*)d_in[8];
    const float* b1    = (const float*)d_in[9];
    const float* Wm    = (const float*)d_in[10];
    const float* bm    = (const float*)d_in[11];
    const float* Ws    = (const float*)d_in[12];
    const float* bs    = (const float*)d_in[13];
    float* out = (float*)d_out;

    norms_kernel<<<32, 256>>>(emb1, emb2);

    dim3 gg(NN / 128, NN / 128);
    // branch 0 (emb1)
    knn_gemm<<<gg, 256>>>(emb1, 0);
    knn_select<<<NN / 8, 256>>>(0);
    // branch 1 (emb2)
    knn_gemm<<<gg, 256>>>(emb2, 1);
    knn_select<<<NN / 8, 256>>>(1);

    gather_mlp<<<BQ / 8, 256>>>(timev, idx1, idx2, resid, means, stds,
                                W1, b1, Wm, bm, Ws, bs, out);
}